// round 6
// baseline (speedup 1.0000x reference)
#include <cuda_runtime.h>
#include <cuda_bf16.h>

// MX quantize-dequantize: block size 32, E8M0 shared scale, E4M3 elements.
// v3: 16 elements/thread, MLP_p1=4, with BOTH 8-element chunks warp-local:
// each warp sweeps one contiguous 2KB window (chunk B = +1KB within the warp
// window), preserving the contiguous DRAM wavefront that v1 had while
// doubling per-thread memory-level parallelism. Interleaved shfl reductions,
// streaming (.cs) loads/stores, exact pow2 bit-constructed scale math.

__device__ __forceinline__ float mx_qdq_elem(float v, float inv_scale, float scale) {
    unsigned sbit = __float_as_uint(v) & 0x80000000u;
    float mag = fabsf(v) * inv_scale;          // exact pow2 multiply
    mag = fminf(mag, 448.0f);                  // E4M3 saturate
    float safe = fmaxf(mag, 0.015625f);        // 2^-6 (subnormal region -> emin)
    int e = (int)(__float_as_uint(safe) >> 23) - 127;
    float quantum = __uint_as_float((unsigned)((e - 3) + 127) << 23); // 2^(e-3)
    float invq    = __uint_as_float((unsigned)((3 - e) + 127) << 23); // 2^(3-e)
    float q = rintf(mag * invq) * quantum * scale; // round-half-even, dequant
    return __uint_as_float(__float_as_uint(q) | sbit);
}

__device__ __forceinline__ float amax8(const float4& a, const float4& b) {
    return fmaxf(fmaxf(fmaxf(fabsf(a.x), fabsf(a.y)), fmaxf(fabsf(a.z), fabsf(a.w))),
                 fmaxf(fmaxf(fabsf(b.x), fabsf(b.y)), fmaxf(fabsf(b.z), fabsf(b.w))));
}

__device__ __forceinline__ void scales_from_amax(float m, float& scale, float& inv_scale) {
    // shared_exp = floor(log2(amax)) - 8, clamped so the pow2 floats stay normal.
    // amax==0 -> all elements zero -> scale irrelevant.
    int se = ((int)(__float_as_uint(m) >> 23) - 127) - 8;
    se = max(se, -126);
    scale     = __uint_as_float((unsigned)(se + 127) << 23);
    inv_scale = __uint_as_float((unsigned)(127 - se) << 23);
}

__device__ __forceinline__ float4 qdq4(const float4& a, float inv_scale, float scale) {
    float4 o;
    o.x = mx_qdq_elem(a.x, inv_scale, scale);
    o.y = mx_qdq_elem(a.y, inv_scale, scale);
    o.z = mx_qdq_elem(a.z, inv_scale, scale);
    o.w = mx_qdq_elem(a.w, inv_scale, scale);
    return o;
}

__global__ void __launch_bounds__(256)
mx_qdq_kernel(const float4* __restrict__ x, float4* __restrict__ y, int nvec) {
    int t    = blockIdx.x * blockDim.x + threadIdx.x;
    int lane = t & 31;
    int warp = t >> 5;
    // Each warp owns 128 consecutive float4s (2KB). Lane l: A at +2l, B at +64+2l.
    int i0 = warp * 128 + lane * 2;  // chunk A pair
    int i1 = i0 + 64;                // chunk B pair (same warp window, +1KB)
    if (i1 + 1 >= nvec) {
        if (i0 + 1 < nvec) {
            float4 a0 = __ldcs(&x[i0]);
            float4 a1 = __ldcs(&x[i0 + 1]);
            float m = amax8(a0, a1);
            m = fmaxf(m, __shfl_xor_sync(0xffffffffu, m, 1));
            m = fmaxf(m, __shfl_xor_sync(0xffffffffu, m, 2));
            float s, is; scales_from_amax(m, s, is);
            __stcs(&y[i0],     qdq4(a0, is, s));
            __stcs(&y[i0 + 1], qdq4(a1, is, s));
        }
        return;
    }

    // Front-batch all 4 loads: MLP_p1 = 4, one contiguous 2KB warp window
    float4 a0 = __ldcs(&x[i0]);
    float4 a1 = __ldcs(&x[i0 + 1]);
    float4 b0 = __ldcs(&x[i1]);
    float4 b1 = __ldcs(&x[i1 + 1]);

    float mA = amax8(a0, a1);
    float mB = amax8(b0, b1);

    // Interleave the two 4-lane reductions so SHFL latency overlaps
    float mA1 = __shfl_xor_sync(0xffffffffu, mA, 1);
    float mB1 = __shfl_xor_sync(0xffffffffu, mB, 1);
    mA = fmaxf(mA, mA1);
    mB = fmaxf(mB, mB1);
    float mA2 = __shfl_xor_sync(0xffffffffu, mA, 2);
    float mB2 = __shfl_xor_sync(0xffffffffu, mB, 2);
    mA = fmaxf(mA, mA2);
    mB = fmaxf(mB, mB2);

    float sA, isA, sB, isB;
    scales_from_amax(mA, sA, isA);
    scales_from_amax(mB, sB, isB);

    __stcs(&y[i0],     qdq4(a0, isA, sA));
    __stcs(&y[i0 + 1], qdq4(a1, isA, sA));
    __stcs(&y[i1],     qdq4(b0, isB, sB));
    __stcs(&y[i1 + 1], qdq4(b1, isB, sB));
}

extern "C" void kernel_launch(void* const* d_in, const int* in_sizes, int n_in,
                              void* d_out, int out_size) {
    const float* x = (const float*)d_in[0];
    float*       y = (float*)d_out;
    int n    = in_sizes[0];        // 33,554,432 (divisible by 32)
    int nvec = n / 4;              // 8,388,608 float4
    int nthreads = nvec / 4;       // 16 elements per thread -> 2,097,152 threads
    int block = 256;
    int grid  = (nthreads + block - 1) / block;  // 8192
    mx_qdq_kernel<<<grid, block>>>((const float4*)x, (float4*)y, nvec);
}

// round 8
// speedup vs baseline: 1.0300x; 1.0300x over previous
#include <cuda_runtime.h>
#include <cuda_bf16.h>

// MX quantize-dequantize: block size 32, E8M0 shared scale, E4M3 elements.
// v4: minimize MLP_p1. 4 elements/thread (single LDG.128), 8 lanes per
// 32-element MX block, amax via 3 shfl.xor steps (1,2,4). No cache hints
// (plain LDG/STG — the .cs variants regressed). Latency hiding comes from
// warp count (32768 CTAs), avoiding the cross-CTA L1tex-queue contention
// that penalized front-batched multi-LDG threads. Exact pow2 bit math.

__device__ __forceinline__ float mx_qdq_elem(float v, float inv_scale, float scale) {
    unsigned sbit = __float_as_uint(v) & 0x80000000u;
    float mag = fabsf(v) * inv_scale;          // exact pow2 multiply
    mag = fminf(mag, 448.0f);                  // E4M3 saturate
    float safe = fmaxf(mag, 0.015625f);        // 2^-6 (subnormal region -> emin)
    int e = (int)(__float_as_uint(safe) >> 23) - 127;
    float quantum = __uint_as_float((unsigned)((e - 3) + 127) << 23); // 2^(e-3)
    float invq    = __uint_as_float((unsigned)((3 - e) + 127) << 23); // 2^(3-e)
    float q = rintf(mag * invq) * quantum * scale; // round-half-even, dequant
    return __uint_as_float(__float_as_uint(q) | sbit);
}

__global__ void __launch_bounds__(256)
mx_qdq_kernel(const float4* __restrict__ x, float4* __restrict__ y, int nvec) {
    int i = blockIdx.x * blockDim.x + threadIdx.x;   // one float4 per thread
    if (i >= nvec) return;

    float4 a = x[i];

    // per-thread amax over 4 elements
    float m = fmaxf(fmaxf(fabsf(a.x), fabsf(a.y)), fmaxf(fabsf(a.z), fabsf(a.w)));

    // reduce across the 8 lanes sharing this 32-element MX block
    m = fmaxf(m, __shfl_xor_sync(0xffffffffu, m, 1));
    m = fmaxf(m, __shfl_xor_sync(0xffffffffu, m, 2));
    m = fmaxf(m, __shfl_xor_sync(0xffffffffu, m, 4));

    // shared_exp = floor(log2(amax)) - 8, exact via exponent field; clamp keeps
    // the bit-constructed pow2 floats normal. amax==0 -> all outputs 0 anyway.
    int se = ((int)(__float_as_uint(m) >> 23) - 127) - 8;
    se = max(se, -126);
    float scale     = __uint_as_float((unsigned)(se + 127) << 23);
    float inv_scale = __uint_as_float((unsigned)(127 - se) << 23);

    float4 o;
    o.x = mx_qdq_elem(a.x, inv_scale, scale);
    o.y = mx_qdq_elem(a.y, inv_scale, scale);
    o.z = mx_qdq_elem(a.z, inv_scale, scale);
    o.w = mx_qdq_elem(a.w, inv_scale, scale);

    y[i] = o;
}

extern "C" void kernel_launch(void* const* d_in, const int* in_sizes, int n_in,
                              void* d_out, int out_size) {
    const float* x = (const float*)d_in[0];
    float*       y = (float*)d_out;
    int n    = in_sizes[0];        // 33,554,432 (divisible by 32)
    int nvec = n / 4;              // 8,388,608 float4 = one per thread
    int block = 256;
    int grid  = (nvec + block - 1) / block;  // 32768
    mx_qdq_kernel<<<grid, block>>>((const float4*)x, (float4*)y, nvec);
}

// round 9
// speedup vs baseline: 1.0846x; 1.0530x over previous
#include <cuda_runtime.h>
#include <cuda_bf16.h>

// MX quantize-dequantize: block size 32, E8M0 shared scale, E4M3 elements.
// v5: R1's winning shape (2x LDG.128/thread, 8 elem/thread, grid 16384) but
// with INTERLEAVED lane mapping: warp owns 64 consecutive float4; lane l
// loads base+l and base+32+l. Every LDG/STG instruction is a contiguous
// 512B warp access (4 cache lines, minimal L1tex wavefronts) instead of
// R1's stride-2 pattern (16 half-consumed lines per instruction). Each
// float4 sits wholly in one MX block; lanes 8k..8k+7 share a block per
// load -> two independent 8-lane shfl reductions, interleaved. Exact pow2
// bit-constructed scale math throughout.

__device__ __forceinline__ float mx_qdq_elem(float v, float inv_scale, float scale) {
    unsigned sbit = __float_as_uint(v) & 0x80000000u;
    float mag = fabsf(v) * inv_scale;          // exact pow2 multiply
    mag = fminf(mag, 448.0f);                  // E4M3 saturate
    float safe = fmaxf(mag, 0.015625f);        // 2^-6 (subnormal region -> emin)
    int e = (int)(__float_as_uint(safe) >> 23) - 127;
    float quantum = __uint_as_float((unsigned)((e - 3) + 127) << 23); // 2^(e-3)
    float invq    = __uint_as_float((unsigned)((3 - e) + 127) << 23); // 2^(3-e)
    float q = rintf(mag * invq) * quantum * scale; // round-half-even, dequant
    return __uint_as_float(__float_as_uint(q) | sbit);
}

__device__ __forceinline__ float amax4(const float4& a) {
    return fmaxf(fmaxf(fabsf(a.x), fabsf(a.y)), fmaxf(fabsf(a.z), fabsf(a.w)));
}

__device__ __forceinline__ void scales_from_amax(float m, float& scale, float& inv_scale) {
    // shared_exp = floor(log2(amax)) - 8, exact via exponent-field extract;
    // clamp keeps the bit-constructed pow2 floats normal. amax==0 -> all
    // elements are zero -> scale value irrelevant.
    int se = ((int)(__float_as_uint(m) >> 23) - 127) - 8;
    se = max(se, -126);
    scale     = __uint_as_float((unsigned)(se + 127) << 23);
    inv_scale = __uint_as_float((unsigned)(127 - se) << 23);
}

__device__ __forceinline__ float4 qdq4(const float4& a, float inv_scale, float scale) {
    float4 o;
    o.x = mx_qdq_elem(a.x, inv_scale, scale);
    o.y = mx_qdq_elem(a.y, inv_scale, scale);
    o.z = mx_qdq_elem(a.z, inv_scale, scale);
    o.w = mx_qdq_elem(a.w, inv_scale, scale);
    return o;
}

__global__ void __launch_bounds__(256)
mx_qdq_kernel(const float4* __restrict__ x, float4* __restrict__ y, int nvec) {
    int t    = blockIdx.x * blockDim.x + threadIdx.x;
    int lane = t & 31;
    int warp = t >> 5;
    int base = warp * 64;          // warp window: 64 consecutive float4 (1KB)
    int i0 = base + lane;          // load A: contiguous 512B across the warp
    int i1 = base + 32 + lane;     // load B: next contiguous 512B

    if (i1 >= nvec) {
        if (i0 < nvec) {
            float4 a = x[i0];
            float m = amax4(a);
            m = fmaxf(m, __shfl_xor_sync(0xffffffffu, m, 1));
            m = fmaxf(m, __shfl_xor_sync(0xffffffffu, m, 2));
            m = fmaxf(m, __shfl_xor_sync(0xffffffffu, m, 4));
            float s, is; scales_from_amax(m, s, is);
            y[i0] = qdq4(a, is, s);
        }
        return;
    }

    float4 a = x[i0];
    float4 b = x[i1];

    float mA = amax4(a);
    float mB = amax4(b);

    // Two independent 8-lane reductions (lanes 8k..8k+7 share one MX block
    // for each load); interleave so SHFL latency overlaps.
    float tA = __shfl_xor_sync(0xffffffffu, mA, 1);
    float tB = __shfl_xor_sync(0xffffffffu, mB, 1);
    mA = fmaxf(mA, tA);
    mB = fmaxf(mB, tB);
    tA = __shfl_xor_sync(0xffffffffu, mA, 2);
    tB = __shfl_xor_sync(0xffffffffu, mB, 2);
    mA = fmaxf(mA, tA);
    mB = fmaxf(mB, tB);
    tA = __shfl_xor_sync(0xffffffffu, mA, 4);
    tB = __shfl_xor_sync(0xffffffffu, mB, 4);
    mA = fmaxf(mA, tA);
    mB = fmaxf(mB, tB);

    float sA, isA, sB, isB;
    scales_from_amax(mA, sA, isA);
    scales_from_amax(mB, sB, isB);

    y[i0] = qdq4(a, isA, sA);
    y[i1] = qdq4(b, isB, sB);
}

extern "C" void kernel_launch(void* const* d_in, const int* in_sizes, int n_in,
                              void* d_out, int out_size) {
    const float* x = (const float*)d_in[0];
    float*       y = (float*)d_out;
    int n    = in_sizes[0];        // 33,554,432 (divisible by 32)
    int nvec = n / 4;              // 8,388,608 float4
    int nthreads = nvec / 2;       // 8 elements per thread
    int block = 256;
    int grid  = (nthreads + block - 1) / block;  // 16384
    mx_qdq_kernel<<<grid, block>>>((const float4*)x, (float4*)y, nvec);
}